// round 15
// baseline (speedup 1.0000x reference)
#include <cuda_runtime.h>
#include <cuda_fp16.h>
#include <cstdint>

#define BATCH 32768
#define NF 162
#define KPAD 176
#define ACCN 1024
#define XW 2048
#define NB 8
#define NTB 40                 // 128-row tile slots per bucket (capacity 5120 rows)
#define MAXT2 (NB * NTB)       // 320 tiles

// ---------------- scratch ----------------
__device__ __half g_F[(size_t)2 * BATCH * KPAD];
__device__ __half g_X[(size_t)BATCH * XW];
__device__ __half g_Wt[(size_t)KPAD * ACCN];         // W_acc^T k-major, zero-padded
__device__ __half g_W1t[XW * 256];                   // W1^T [k][n]
__device__ float  g_psqt_s[BATCH];
__device__ float  g_psqt_n[BATCH];
__device__ int    g_cnt[NB];                         // zero at load; snapshotted+zeroed by gemm1
__device__ int    g_cnt2[NB];                        // stable copy for gemm2
__device__ int    g_perm[NB * BATCH];

__device__ __forceinline__ uint32_t smem_u32(const void* p) {
    return (uint32_t)__cvta_generic_to_shared(p);
}

// ---------------- prep: tiled transposes + feature packing (MLP-forced) ----------------
#define WACC_BLKS 192
#define W1_BLKS 512
#define FEAT_BASE (WACC_BLKS + W1_BLKS)

__global__ void __launch_bounds__(256, 2) prep_kernel(const float* __restrict__ stm,
                                                      const float* __restrict__ nstm,
                                                      const float* __restrict__ Wacc,
                                                      const float* __restrict__ W1) {
    const int bid = blockIdx.x;
    if (bid < FEAT_BASE) {
        __shared__ float s[32][33];
        const int tx = threadIdx.x & 31, ty = threadIdx.x >> 5;   // 32 x 8
        if (bid < WACC_BLKS) {
            const int j0 = (bid & 31) * 32, k0 = (bid >> 5) * 32;
            #pragma unroll
            for (int r = 0; r < 4; ++r) {
                int j = j0 + ty + r * 8, k = k0 + tx;
                s[ty + r * 8][tx] = (k < NF) ? Wacc[(size_t)j * NF + k] : 0.f;
            }
            __syncthreads();
            #pragma unroll
            for (int r = 0; r < 4; ++r) {
                int k = k0 + ty + r * 8;
                if (k < KPAD) g_Wt[(size_t)k * ACCN + j0 + tx] = __float2half_rn(s[tx][ty + r * 8]);
            }
        } else {
            const int q = bid - WACC_BLKS;
            const int n0 = (q & 7) * 32, k0 = (q >> 3) * 32;
            #pragma unroll
            for (int r = 0; r < 4; ++r)
                s[ty + r * 8][tx] = W1[(size_t)(n0 + ty + r * 8) * XW + k0 + tx];
            __syncthreads();
            #pragma unroll
            for (int r = 0; r < 4; ++r)
                g_W1t[(size_t)(k0 + ty + r * 8) * 256 + n0 + tx] =
                    __float2half_rn(s[tx][ty + r * 8]);
        }
        return;
    }
    // feature part: one warp handles stm row w AND nstm row w; ALL loads issued first
    int w = ((bid - FEAT_BASE) * 256 + threadIdx.x) >> 5;
    int lane = threadIdx.x & 31;
    if (w >= BATCH) return;
    const float2* WaccLast = (const float2*)(Wacc + (size_t)ACCN * NF);
    const float2* srcs = (const float2*)(stm  + (size_t)w * NF);
    const float2* srcn = (const float2*)(nstm + (size_t)w * NF);

    float2 vs[3], vn[3], wl[3];
    #pragma unroll
    for (int it = 0; it < 3; ++it) {
        const int p = lane + it * 32;
        const bool ok = (p < 81);
        vs[it] = ok ? srcs[p] : make_float2(0.f, 0.f);
        vn[it] = ok ? srcn[p] : make_float2(0.f, 0.f);
        wl[it] = ok ? WaccLast[p] : make_float2(0.f, 0.f);
    }

    __half2* dsts = (__half2*)(g_F + (size_t)w * KPAD);
    __half2* dstn = (__half2*)(g_F + (size_t)(BATCH + w) * KPAD);
    float cnt = 0.f, pss = 0.f, psn = 0.f;
    #pragma unroll
    for (int it = 0; it < 3; ++it) {
        const int p = lane + it * 32;
        pss += vs[it].x * wl[it].x + vs[it].y * wl[it].y;
        psn += vn[it].x * wl[it].x + vn[it].y * wl[it].y;
        cnt += vs[it].x + vs[it].y;
        if (p < 88) {
            dsts[p] = __floats2half2_rn(vs[it].x, vs[it].y);
            dstn[p] = __floats2half2_rn(vn[it].x, vn[it].y);
        }
    }
    #pragma unroll
    for (int o = 16; o; o >>= 1) {
        cnt += __shfl_xor_sync(0xffffffffu, cnt, o);
        pss += __shfl_xor_sync(0xffffffffu, pss, o);
        psn += __shfl_xor_sync(0xffffffffu, psn, o);
    }
    if (lane == 0) {
        int pc = (int)(cnt + 0.5f);
        int b  = pc / 20;
        b = (b > NB - 1) ? NB - 1 : b;
        int pos = atomicAdd(&g_cnt[b], 1);
        g_perm[b * BATCH + pos] = w;
        g_psqt_s[w] = pss;
        g_psqt_n[w] = psn;
    }
}

// ---------------- GEMM1: proven R3/R6 version (BN=128, 103us measured) ----------------
#define BSTR 136
#define ASTR 184
#define G1_SMEM ((KPAD * BSTR + 2 * 128 * ASTR) * 2)

__global__ void __launch_bounds__(512) gemm1_kernel(const float* __restrict__ bias) {
    extern __shared__ __half sh[];
    __half* Bs = sh;                       // [176][BSTR]
    __half* As = sh + KPAD * BSTR;         // [2][128][ASTR]

    const int tid  = threadIdx.x;
    const int lane = tid & 31, wid = tid >> 5;
    const int wm = wid & 3, wn = wid >> 2;          // 4x4 warps, warp tile 32x32
    const int n0 = blockIdx.y * 128;
    const int mslot = blockIdx.x;                   // 0..17

    if (blockIdx.x == 0 && blockIdx.y == 0 && tid < NB) {
        g_cnt2[tid] = g_cnt[tid];                   // snapshot for gemm2
        g_cnt[tid] = 0;                             // clean state for next replay
    }

    for (int idx = tid; idx < KPAD * 16; idx += 512) {
        int k = idx >> 4, c = idx & 15;
        asm volatile("cp.async.cg.shared.global [%0], [%1], 16;\n"
                     :: "r"(smem_u32(Bs + k * BSTR + c * 8)),
                        "l"(g_Wt + (size_t)k * ACCN + n0 + c * 8));
    }

    auto loadA = [&](int buf, int mt) {
        const __half* base = g_F + (size_t)mt * 128 * KPAD;
        __half* dst = As + buf * (128 * ASTR);
        #pragma unroll
        for (int it = 0; it < 6; ++it) {
            int idx = tid + it * 512;                // 128 x 22 chunks
            if (idx < 128 * 22) {
                int r = idx / 22, c = idx - r * 22;
                asm volatile("cp.async.cg.shared.global [%0], [%1], 16;\n"
                             :: "r"(smem_u32(dst + r * ASTR + c * 8)),
                                "l"(base + (size_t)r * KPAD + c * 8));
            }
        }
    };

    loadA(0, mslot);
    asm volatile("cp.async.commit_group;\n");
    const int jmax = (512 - mslot + 17) / 18;
    if (jmax > 1) loadA(1, mslot + 18);
    asm volatile("cp.async.commit_group;\n");

    const int g = lane >> 2, t4 = lane & 3;
    int buf = 0;
    for (int j = 0; j < jmax; ++j) {
        const int mt = mslot + j * 18;
        asm volatile("cp.async.wait_group 1;\n");
        __syncthreads();

        float acc[2][4][4];
        #pragma unroll
        for (int i = 0; i < 2; ++i)
            #pragma unroll
            for (int jj = 0; jj < 4; ++jj)
                #pragma unroll
                for (int k = 0; k < 4; ++k) acc[i][jj][k] = 0.f;

        const __half* Ab = As + buf * (128 * ASTR);
        #pragma unroll
        for (int kt = 0; kt < 11; ++kt) {
            uint32_t af[2][4], bf[4][2];
            #pragma unroll
            for (int mf = 0; mf < 2; ++mf) {
                const __half* p = Ab + (wm * 32 + mf * 16 + ((lane >> 3) & 1) * 8 + (lane & 7)) * ASTR
                                     + kt * 16 + (lane >> 4) * 8;
                asm volatile("ldmatrix.sync.aligned.m8n8.x4.shared.b16 {%0,%1,%2,%3}, [%4];\n"
                             : "=r"(af[mf][0]), "=r"(af[mf][1]), "=r"(af[mf][2]), "=r"(af[mf][3])
                             : "r"(smem_u32(p)));
            }
            #pragma unroll
            for (int ng = 0; ng < 2; ++ng) {
                const __half* p = Bs + (kt * 16 + ((lane >> 3) & 1) * 8 + (lane & 7)) * BSTR
                                     + wn * 32 + ng * 16 + (lane >> 4) * 8;
                uint32_t r0, r1, r2, r3;
                asm volatile("ldmatrix.sync.aligned.m8n8.x4.trans.shared.b16 {%0,%1,%2,%3}, [%4];\n"
                             : "=r"(r0), "=r"(r1), "=r"(r2), "=r"(r3) : "r"(smem_u32(p)));
                bf[ng * 2 + 0][0] = r0; bf[ng * 2 + 0][1] = r1;
                bf[ng * 2 + 1][0] = r2; bf[ng * 2 + 1][1] = r3;
            }
            #pragma unroll
            for (int mf = 0; mf < 2; ++mf)
                #pragma unroll
                for (int nf = 0; nf < 4; ++nf)
                    asm volatile(
                        "mma.sync.aligned.m16n8k16.row.col.f32.f16.f16.f32 "
                        "{%0,%1,%2,%3}, {%4,%5,%6,%7}, {%8,%9}, {%0,%1,%2,%3};\n"
                        : "+f"(acc[mf][nf][0]), "+f"(acc[mf][nf][1]),
                          "+f"(acc[mf][nf][2]), "+f"(acc[mf][nf][3])
                        : "r"(af[mf][0]), "r"(af[mf][1]), "r"(af[mf][2]), "r"(af[mf][3]),
                          "r"(bf[nf][0]), "r"(bf[nf][1]));
        }
        __syncthreads();

        if (j + 2 < jmax) loadA(buf, mslot + (j + 2) * 18);
        asm volatile("cp.async.commit_group;\n");

        // epilogue: bias + clip^2 -> g_X
        #pragma unroll
        for (int mf = 0; mf < 2; ++mf) {
            #pragma unroll
            for (int nf = 0; nf < 4; ++nf) {
                const int col = n0 + wn * 32 + nf * 8 + 2 * t4;
                #pragma unroll
                for (int h = 0; h < 2; ++h) {
                    const int row = mt * 128 + wm * 32 + mf * 16 + g + h * 8;
                    float v0 = __saturatef(acc[mf][nf][h * 2 + 0] + bias[col]);     v0 *= v0;
                    float v1 = __saturatef(acc[mf][nf][h * 2 + 1] + bias[col + 1]); v1 *= v1;
                    const size_t off = (row < BATCH)
                        ? (size_t)row * XW + col
                        : (size_t)(row - BATCH) * XW + ACCN + col;
                    *(__half2*)(g_X + off) = __floats2half2_rn(v0, v1);
                }
            }
        }
        buf ^= 1;
    }
}

// ---------------- GEMM2: 128-row tiles, BK=32, 4-stage ring, fused tail (proven 47us) ----------------
#define A2STR 40
#define STG_A (128 * A2STR)
#define STG_B (32 * A2STR)
#define STG_H (STG_A + STG_B)
#define G2_DYN (4 * STG_H * 2)     // 51200 bytes; overlay (21.3 KB) fits inside

__global__ void __launch_bounds__(256) gemm2_kernel(const float* __restrict__ b1,
                                                    const float* __restrict__ W2,
                                                    const float* __restrict__ b2,
                                                    const float* __restrict__ W3,
                                                    const float* __restrict__ b3,
                                                    float* __restrict__ out) {
    extern __shared__ char dyn[];
    __half* stg = (__half*)dyn;                       // [4][STG_H]
    float* sh1  = (float*)dyn;                        // overlay after main loop
    float* sW2  = sh1 + 128 * 33;
    float* sb2  = sW2 + 1024;
    float* sW3  = sb2 + 32;
    float* sb3p = sW3 + 32;
    __shared__ int sperm[128];

    const int bk = blockIdx.x / NTB, i = blockIdx.x - bk * NTB;
    const int cnt = g_cnt2[bk];
    if (i * 128 >= cnt) return;

    const int tid  = threadIdx.x;
    const int lane = tid & 31, wid = tid >> 5;
    const int wm = wid & 3, wn = wid >> 2;            // warp tile 32m x 16n

    if (tid < 128) {
        int p = i * 128 + tid;
        sperm[tid] = (p < cnt) ? g_perm[bk * BATCH + p] : -1;
    }
    __syncthreads();

    const int arow = tid >> 1;
    const int ac2  = (tid & 1) * 2;
    int rp = sperm[arow]; if (rp < 0) rp = 0;
    const __half* gA = g_X + (size_t)rp * XW + ac2 * 8;
    const int brow = tid >> 2, bc = tid & 3;
    const __half* gB = g_W1t + (size_t)brow * 256 + bk * 32 + bc * 8;

    auto issue = [&](int kt) {
        __half* base = stg + (kt & 3) * STG_H;
        uint32_t sa = smem_u32(base + arow * A2STR + ac2 * 8);
        #pragma unroll
        for (int c = 0; c < 2; ++c)
            asm volatile("cp.async.cg.shared.global [%0], [%1], 16;\n"
                         :: "r"(sa + c * 16), "l"(gA + kt * 32 + c * 8));
        if (tid < 128) {
            uint32_t sb = smem_u32(base + STG_A + brow * A2STR + bc * 8);
            asm volatile("cp.async.cg.shared.global [%0], [%1], 16;\n"
                         :: "r"(sb), "l"(gB + (size_t)kt * 32 * 256));
        }
        asm volatile("cp.async.commit_group;\n");
    };

    float acc[2][2][4];
    #pragma unroll
    for (int i2 = 0; i2 < 2; ++i2)
        #pragma unroll
        for (int j = 0; j < 2; ++j)
            #pragma unroll
            for (int k = 0; k < 4; ++k) acc[i2][j][k] = 0.f;

    issue(0); issue(1); issue(2);

    const int KT = XW / 32;   // 64
    for (int kt = 0; kt < KT; ++kt) {
        asm volatile("cp.async.wait_group 2;\n");
        __syncthreads();

        const __half* Ab = stg + (kt & 3) * STG_H;
        const __half* Bb = Ab + STG_A;
        #pragma unroll
        for (int ks = 0; ks < 2; ++ks) {
            uint32_t af[2][4], bf[2][2];
            #pragma unroll
            for (int mf = 0; mf < 2; ++mf) {
                const __half* p = Ab + (wm * 32 + mf * 16 + ((lane >> 3) & 1) * 8 + (lane & 7)) * A2STR
                                     + ks * 16 + (lane >> 4) * 8;
                asm volatile("ldmatrix.sync.aligned.m8n8.x4.shared.b16 {%0,%1,%2,%3}, [%4];\n"
                             : "=r"(af[mf][0]), "=r"(af[mf][1]), "=r"(af[mf][2]), "=r"(af[mf][3])
                             : "r"(smem_u32(p)));
            }
            {
                const __half* p = Bb + (ks * 16 + ((lane >> 3) & 1) * 8 + (lane & 7)) * A2STR
                                     + wn * 16 + (lane >> 4) * 8;
                uint32_t r0, r1, r2, r3;
                asm volatile("ldmatrix.sync.aligned.m8n8.x4.trans.shared.b16 {%0,%1,%2,%3}, [%4];\n"
                             : "=r"(r0), "=r"(r1), "=r"(r2), "=r"(r3) : "r"(smem_u32(p)));
                bf[0][0] = r0; bf[0][1] = r1;
                bf[1][0] = r2; bf[1][1] = r3;
            }
            #pragma unroll
            for (int mf = 0; mf < 2; ++mf)
                #pragma unroll
                for (int nf = 0; nf < 2; ++nf)
                    asm volatile(
                        "mma.sync.aligned.m16n8k16.row.col.f32.f16.f16.f32 "
                        "{%0,%1,%2,%3}, {%4,%5,%6,%7}, {%8,%9}, {%0,%1,%2,%3};\n"
                        : "+f"(acc[mf][nf][0]), "+f"(acc[mf][nf][1]),
                          "+f"(acc[mf][nf][2]), "+f"(acc[mf][nf][3])
                        : "r"(af[mf][0]), "r"(af[mf][1]), "r"(af[mf][2]), "r"(af[mf][3]),
                          "r"(bf[nf][0]), "r"(bf[nf][1]));
        }

        if (kt + 3 < KT) issue(kt + 3);
        else asm volatile("cp.async.commit_group;\n");
    }

    __syncthreads();   // all stage reads done -> overlay is safe

    // epilogue into overlay + load tail weights
    const int g = lane >> 2, t4 = lane & 3;
    #pragma unroll
    for (int mf = 0; mf < 2; ++mf) {
        #pragma unroll
        for (int nf = 0; nf < 2; ++nf) {
            const int col = wn * 16 + nf * 8 + 2 * t4;
            #pragma unroll
            for (int h = 0; h < 2; ++h) {
                const int rl = wm * 32 + mf * 16 + g + h * 8;
                sh1[rl * 33 + col]     = __saturatef(acc[mf][nf][h * 2 + 0] + b1[bk * 32 + col]);
                sh1[rl * 33 + col + 1] = __saturatef(acc[mf][nf][h * 2 + 1] + b1[bk * 32 + col + 1]);
            }
        }
    }
    for (int idx = tid; idx < 1024; idx += 256) sW2[idx] = W2[bk * 1024 + idx];
    if (tid < 32) { sb2[tid] = b2[bk * 32 + tid]; sW3[tid] = W3[bk * 32 + tid]; }
    if (tid == 0) *sb3p = b3[bk];
    __syncthreads();

    if (tid < 128) {
        const int r = sperm[tid];
        if (r >= 0) {
            const float* hr = &sh1[tid * 33];
            float o = 0.f;
            #pragma unroll 4
            for (int ii = 0; ii < 32; ++ii) {
                float s = sb2[ii];
                const float* wr = &sW2[ii * 32];
                #pragma unroll
                for (int j = 0; j < 32; ++j) s += wr[j] * hr[j];
                s = __saturatef(s);
                o += sW3[ii] * s;
            }
            o += *sb3p + 0.5f * (g_psqt_s[r] - g_psqt_n[r]);
            out[r] = o;
        }
    }
}

// ---------------- launch ----------------
extern "C" void kernel_launch(void* const* d_in, const int* in_sizes, int n_in,
                              void* d_out, int out_size) {
    const float* stm  = (const float*)d_in[0];
    const float* nstm = (const float*)d_in[1];
    const float* Wacc = (const float*)d_in[2];
    const float* bacc = (const float*)d_in[3];
    const float* W1   = (const float*)d_in[4];
    const float* b1   = (const float*)d_in[5];
    const float* W2   = (const float*)d_in[6];
    const float* b2   = (const float*)d_in[7];
    const float* W3   = (const float*)d_in[8];
    const float* b3   = (const float*)d_in[9];
    float* out = (float*)d_out;

    static bool attr_set = false;
    if (!attr_set) {
        cudaFuncSetAttribute(gemm1_kernel, cudaFuncAttributeMaxDynamicSharedMemorySize, G1_SMEM);
        cudaFuncSetAttribute(gemm2_kernel, cudaFuncAttributeMaxDynamicSharedMemorySize, G2_DYN);
        attr_set = true;
    }

    prep_kernel<<<FEAT_BASE + BATCH / 8, 256>>>(stm, nstm, Wacc, W1);

    dim3 g1(18, ACCN / 128);
    gemm1_kernel<<<g1, 512, G1_SMEM>>>(bacc);

    gemm2_kernel<<<MAXT2, 256, G2_DYN>>>(b1, W2, b2, W3, b3, out);
}

// round 16
// speedup vs baseline: 1.1074x; 1.1074x over previous
#include <cuda_runtime.h>
#include <cuda_fp16.h>
#include <cstdint>

#define BATCH 32768
#define NF 162
#define KPAD 176
#define ACCN 1024
#define XW 2048
#define NB 8
#define NTB 40                 // 128-row tile slots per bucket (capacity 5120 rows)
#define MAXT2 (NB * NTB)       // 320 tiles

// ---------------- scratch ----------------
__device__ __half g_F[(size_t)2 * BATCH * KPAD];
__device__ __half g_Wt[(size_t)KPAD * ACCN];           // W_acc^T k-major, zero-padded
__device__ uint32_t g_Xf[(size_t)MAXT2 * 128 * 8 * 128];   // X in A-frag layout: [tile][kb128][mb8][lane32][4 u32]
__device__ uint32_t g_W1f[NB * 128 * 32 * 8];          // W1 in B-frag layout: [bk][kt128][lane32][8 u32]
__device__ float  g_psqt_s[BATCH];
__device__ float  g_psqt_n[BATCH];
__device__ int    g_cnt[NB];                           // zero at load; snapshotted+zeroed by snap
__device__ int    g_cnt2[NB];
__device__ int    g_perm[NB * BATCH];

__device__ __forceinline__ uint32_t smem_u32(const void* p) {
    return (uint32_t)__cvta_generic_to_shared(p);
}
__device__ __forceinline__ uint32_t packh2(float a, float b) {
    __half2 h = __floats2half2_rn(a, b);
    return *(uint32_t*)&h;
}

// ---------------- prep: Wacc transpose + W1 frag-pack + feature packing ----------------
#define WACC_BLKS 192
#define W1F_BLKS 128
#define FEAT_BASE (WACC_BLKS + W1F_BLKS)

__global__ void __launch_bounds__(256, 2) prep_kernel(const float* __restrict__ stm,
                                                      const float* __restrict__ nstm,
                                                      const float* __restrict__ Wacc,
                                                      const float* __restrict__ W1) {
    const int bid = blockIdx.x;
    if (bid < WACC_BLKS) {
        __shared__ float s[32][33];
        const int tx = threadIdx.x & 31, ty = threadIdx.x >> 5;   // 32 x 8
        const int j0 = (bid & 31) * 32, k0 = (bid >> 5) * 32;
        #pragma unroll
        for (int r = 0; r < 4; ++r) {
            int j = j0 + ty + r * 8, k = k0 + tx;
            s[ty + r * 8][tx] = (k < NF) ? Wacc[(size_t)j * NF + k] : 0.f;
        }
        __syncthreads();
        #pragma unroll
        for (int r = 0; r < 4; ++r) {
            int k = k0 + ty + r * 8;
            if (k < KPAD) g_Wt[(size_t)k * ACCN + j0 + tx] = __float2half_rn(s[tx][ty + r * 8]);
        }
        return;
    }
    if (bid < FEAT_BASE) {
        // W1 -> B-fragment layout. b-frag (k16 x n8): lane (g=lane>>2,t=lane&3):
        // b0 = (W1[N][k0+2t], W1[N][k0+2t+1]), b1 = (W1[N][k0+2t+8], W1[N][k0+2t+9])
        const int q = bid - WACC_BLKS;                 // 0..127
        const int b = q >> 4;
        const int kt = (q & 15) * 8 + (threadIdx.x >> 5);
        const int lane = threadIdx.x & 31;
        const int g = lane >> 2, t = lane & 3;
        uint32_t* dst = g_W1f + ((size_t)(b * 128 + kt) * 32 + lane) * 8;
        #pragma unroll
        for (int nb = 0; nb < 4; ++nb) {
            const float* w = W1 + (size_t)(b * 32 + nb * 8 + g) * XW + kt * 16;
            dst[nb * 2 + 0] = packh2(w[2 * t],     w[2 * t + 1]);
            dst[nb * 2 + 1] = packh2(w[2 * t + 8], w[2 * t + 9]);
        }
        return;
    }
    // feature part: one warp handles stm row w AND nstm row w
    int w = ((bid - FEAT_BASE) * 256 + threadIdx.x) >> 5;
    int lane = threadIdx.x & 31;
    if (w >= BATCH) return;
    const float2* WaccLast = (const float2*)(Wacc + (size_t)ACCN * NF);
    const float2* srcs = (const float2*)(stm  + (size_t)w * NF);
    const float2* srcn = (const float2*)(nstm + (size_t)w * NF);

    float2 vs[3], vn[3], wl[3];
    #pragma unroll
    for (int it = 0; it < 3; ++it) {
        const int p = lane + it * 32;
        const bool ok = (p < 81);
        vs[it] = ok ? srcs[p] : make_float2(0.f, 0.f);
        vn[it] = ok ? srcn[p] : make_float2(0.f, 0.f);
        wl[it] = ok ? WaccLast[p] : make_float2(0.f, 0.f);
    }
    __half2* dsts = (__half2*)(g_F + (size_t)w * KPAD);
    __half2* dstn = (__half2*)(g_F + (size_t)(BATCH + w) * KPAD);
    float cnt = 0.f, pss = 0.f, psn = 0.f;
    #pragma unroll
    for (int it = 0; it < 3; ++it) {
        const int p = lane + it * 32;
        pss += vs[it].x * wl[it].x + vs[it].y * wl[it].y;
        psn += vn[it].x * wl[it].x + vn[it].y * wl[it].y;
        cnt += vs[it].x + vs[it].y;
        if (p < 88) {
            dsts[p] = __floats2half2_rn(vs[it].x, vs[it].y);
            dstn[p] = __floats2half2_rn(vn[it].x, vn[it].y);
        }
    }
    #pragma unroll
    for (int o = 16; o; o >>= 1) {
        cnt += __shfl_xor_sync(0xffffffffu, cnt, o);
        pss += __shfl_xor_sync(0xffffffffu, pss, o);
        psn += __shfl_xor_sync(0xffffffffu, psn, o);
    }
    if (lane == 0) {
        int pc = (int)(cnt + 0.5f);
        int b  = pc / 20;
        b = (b > NB - 1) ? NB - 1 : b;
        int pos = atomicAdd(&g_cnt[b], 1);
        g_perm[b * BATCH + pos] = w;
        g_psqt_s[w] = pss;
        g_psqt_n[w] = psn;
    }
}

__global__ void snap_kernel() {
    if (threadIdx.x < NB) {
        g_cnt2[threadIdx.x] = g_cnt[threadIdx.x];
        g_cnt[threadIdx.x] = 0;
    }
}

// ---------------- GEMM1: proven core, bucket-gathered A, frag-layout STG.128 epilogue ----------------
#define BSTR 136
#define ASTR 184
#define G1_SMEM ((KPAD * BSTR + 2 * 128 * ASTR) * 2)

__global__ void __launch_bounds__(512) gemm1_kernel(const float* __restrict__ bias) {
    extern __shared__ __half sh[];
    __half* Bs = sh;                       // [176][BSTR]
    __half* As = sh + KPAD * BSTR;         // [2][128][ASTR]
    __shared__ float sbias[128];
    __shared__ int scnt[NB];
    __shared__ short slist[40];
    __shared__ int snl;

    const int tid  = threadIdx.x;
    const int lane = tid & 31, wid = tid >> 5;
    const int wm = wid & 3, wn = wid >> 2;          // 4x4 warps, warp tile 32x32
    const int n0 = blockIdx.y * 128;
    const int mslot = blockIdx.x;                   // 0..17

    if (tid < NB) scnt[tid] = g_cnt2[tid];
    if (tid < 128) sbias[tid] = bias[n0 + tid];

    for (int idx = tid; idx < KPAD * 16; idx += 512) {
        int k = idx >> 4, c = idx & 15;
        asm volatile("cp.async.cg.shared.global [%0], [%1], 16;\n"
                     :: "r"(smem_u32(Bs + k * BSTR + c * 8)),
                        "l"(g_Wt + (size_t)k * ACCN + n0 + c * 8));
    }
    __syncthreads();                                 // scnt ready
    if (tid == 0) {
        int L = 0;
        for (int t = mslot; t < 2 * MAXT2; t += 18) {
            int tt = (t >= MAXT2) ? t - MAXT2 : t;
            int b = tt / NTB, i = tt - b * NTB;
            if (i * 128 < scnt[b]) slist[L++] = (short)t;
        }
        snl = L;
    }
    __syncthreads();
    const int L = snl;

    auto loadA = [&](int buf, int le) {
        const int t = slist[le];
        const int plane = (t >= MAXT2) ? 1 : 0;
        const int tt = t - plane * MAXT2;
        const int b = tt / NTB, i = tt - b * NTB;
        const int cb = scnt[b];
        __half* dst = As + buf * (128 * ASTR);
        #pragma unroll
        for (int it = 0; it < 6; ++it) {
            int idx = tid + it * 512;                // 128 rows x 22 chunks
            if (idx < 128 * 22) {
                int r = idx / 22, c = idx - r * 22;
                int pos = i * 128 + r;
                if (pos >= cb) pos = cb - 1;
                int grow = g_perm[b * BATCH + pos] + plane * BATCH;
                asm volatile("cp.async.cg.shared.global [%0], [%1], 16;\n"
                             :: "r"(smem_u32(dst + r * ASTR + c * 8)),
                                "l"(g_F + (size_t)grow * KPAD + c * 8));
            }
        }
    };

    if (L > 0) loadA(0, 0);
    asm volatile("cp.async.commit_group;\n");
    if (L > 1) loadA(1, 1);
    asm volatile("cp.async.commit_group;\n");

    const int g = lane >> 2, t4 = lane & 3;
    int buf = 0;
    for (int j = 0; j < L; ++j) {
        asm volatile("cp.async.wait_group 1;\n");
        __syncthreads();

        const int t = slist[j];
        const int plane = (t >= MAXT2) ? 1 : 0;
        const int gtile = t - plane * MAXT2;         // 0..319

        float acc[2][4][4];
        #pragma unroll
        for (int i = 0; i < 2; ++i)
            #pragma unroll
            for (int jj = 0; jj < 4; ++jj)
                #pragma unroll
                for (int k = 0; k < 4; ++k) acc[i][jj][k] = 0.f;

        const __half* Ab = As + buf * (128 * ASTR);
        #pragma unroll
        for (int kt = 0; kt < 11; ++kt) {
            uint32_t af[2][4], bf[4][2];
            #pragma unroll
            for (int mf = 0; mf < 2; ++mf) {
                const __half* p = Ab + (wm * 32 + mf * 16 + ((lane >> 3) & 1) * 8 + (lane & 7)) * ASTR
                                     + kt * 16 + (lane >> 4) * 8;
                asm volatile("ldmatrix.sync.aligned.m8n8.x4.shared.b16 {%0,%1,%2,%3}, [%4];\n"
                             : "=r"(af[mf][0]), "=r"(af[mf][1]), "=r"(af[mf][2]), "=r"(af[mf][3])
                             : "r"(smem_u32(p)));
            }
            #pragma unroll
            for (int ng = 0; ng < 2; ++ng) {
                const __half* p = Bs + (kt * 16 + ((lane >> 3) & 1) * 8 + (lane & 7)) * BSTR
                                     + wn * 32 + ng * 16 + (lane >> 4) * 8;
                uint32_t r0, r1, r2, r3;
                asm volatile("ldmatrix.sync.aligned.m8n8.x4.trans.shared.b16 {%0,%1,%2,%3}, [%4];\n"
                             : "=r"(r0), "=r"(r1), "=r"(r2), "=r"(r3) : "r"(smem_u32(p)));
                bf[ng * 2 + 0][0] = r0; bf[ng * 2 + 0][1] = r1;
                bf[ng * 2 + 1][0] = r2; bf[ng * 2 + 1][1] = r3;
            }
            #pragma unroll
            for (int mf = 0; mf < 2; ++mf)
                #pragma unroll
                for (int nf = 0; nf < 4; ++nf)
                    asm volatile(
                        "mma.sync.aligned.m16n8k16.row.col.f32.f16.f16.f32 "
                        "{%0,%1,%2,%3}, {%4,%5,%6,%7}, {%8,%9}, {%0,%1,%2,%3};\n"
                        : "+f"(acc[mf][nf][0]), "+f"(acc[mf][nf][1]),
                          "+f"(acc[mf][nf][2]), "+f"(acc[mf][nf][3])
                        : "r"(af[mf][0]), "r"(af[mf][1]), "r"(af[mf][2]), "r"(af[mf][3]),
                          "r"(bf[nf][0]), "r"(bf[nf][1]));
        }
        __syncthreads();

        if (j + 2 < L) loadA(buf, j + 2);
        asm volatile("cp.async.commit_group;\n");

        // epilogue: bias + clip^2 -> g_Xf (A-fragment layout, STG.128)
        #pragma unroll
        for (int mf = 0; mf < 2; ++mf) {
            #pragma unroll
            for (int pr = 0; pr < 2; ++pr) {
                const int cE = wn * 32 + pr * 16 + 2 * t4;   // block-local col of even frag
                float e0 = __saturatef(acc[mf][pr * 2][0] + sbias[cE]);         e0 *= e0;
                float e1 = __saturatef(acc[mf][pr * 2][1] + sbias[cE + 1]);     e1 *= e1;
                float e2 = __saturatef(acc[mf][pr * 2][2] + sbias[cE]);         e2 *= e2;
                float e3 = __saturatef(acc[mf][pr * 2][3] + sbias[cE + 1]);     e3 *= e3;
                float o0 = __saturatef(acc[mf][pr * 2 + 1][0] + sbias[cE + 8]); o0 *= o0;
                float o1 = __saturatef(acc[mf][pr * 2 + 1][1] + sbias[cE + 9]); o1 *= o1;
                float o2 = __saturatef(acc[mf][pr * 2 + 1][2] + sbias[cE + 8]); o2 *= o2;
                float o3 = __saturatef(acc[mf][pr * 2 + 1][3] + sbias[cE + 9]); o3 *= o3;
                uint4 v;
                v.x = packh2(e0, e1);   // row g,   k-lo
                v.y = packh2(e2, e3);   // row g+8, k-lo
                v.z = packh2(o0, o1);   // row g,   k-hi
                v.w = packh2(o2, o3);   // row g+8, k-hi
                const int kb = plane * 64 + (n0 >> 4) + wn * 2 + pr;
                const int mb = wm * 2 + mf;
                uint4* dst = (uint4*)g_Xf + (((size_t)gtile * 128 + kb) * 8 + mb) * 32 + lane;
                *dst = v;
            }
        }
        buf ^= 1;
    }
}

// ---------------- GEMM2: register-direct GEMM from fragment layouts + fused tail ----------------
__global__ void __launch_bounds__(256) gemm2_kernel(const float* __restrict__ b1,
                                                    const float* __restrict__ W2,
                                                    const float* __restrict__ b2,
                                                    const float* __restrict__ W3,
                                                    const float* __restrict__ b3,
                                                    float* __restrict__ out) {
    __shared__ float sh1[128 * 33];
    __shared__ float sW2[1024];
    __shared__ float sb2[32];
    __shared__ float sW3[32];
    __shared__ float sb3v;
    __shared__ float sb1[32];
    __shared__ int sperm[128];

    const int tile = blockIdx.x;
    const int bk = tile / NTB, i = tile - bk * NTB;
    const int cnt = g_cnt2[bk];
    if (i * 128 >= cnt) return;

    const int tid  = threadIdx.x;
    const int lane = tid & 31, wid = tid >> 5;      // warp = m-block (16 rows), covers all 32 n
    const int g = lane >> 2, t4 = lane & 3;

    if (tid < 128) {
        int p = i * 128 + tid;
        sperm[tid] = (p < cnt) ? g_perm[bk * BATCH + p] : -1;
    }
    if (tid < 32) { sb1[tid] = b1[bk * 32 + tid]; sb2[tid] = b2[bk * 32 + tid]; sW3[tid] = W3[bk * 32 + tid]; }
    for (int idx = tid; idx < 1024; idx += 256) sW2[idx] = W2[bk * 1024 + idx];
    if (tid == 0) sb3v = b3[bk];

    const uint4* Ab = (const uint4*)g_Xf + ((size_t)tile * 128 * 8 + wid) * 32 + lane;  // +kt*256
    const uint4* Bb = (const uint4*)g_W1f + ((size_t)bk * 128 * 32 + lane) * 2;          // +kt*64

    float acc[4][4];
    #pragma unroll
    for (int nb = 0; nb < 4; ++nb)
        #pragma unroll
        for (int k = 0; k < 4; ++k) acc[nb][k] = 0.f;

    #pragma unroll 4
    for (int kt = 0; kt < 128; ++kt) {
        const uint4 a  = Ab[(size_t)kt * 256];
        const uint4 b0 = Bb[(size_t)kt * 64];
        const uint4 b1v = Bb[(size_t)kt * 64 + 1];
        asm volatile("mma.sync.aligned.m16n8k16.row.col.f32.f16.f16.f32 "
                     "{%0,%1,%2,%3}, {%4,%5,%6,%7}, {%8,%9}, {%0,%1,%2,%3};\n"
                     : "+f"(acc[0][0]), "+f"(acc[0][1]), "+f"(acc[0][2]), "+f"(acc[0][3])
                     : "r"(a.x), "r"(a.y), "r"(a.z), "r"(a.w), "r"(b0.x), "r"(b0.y));
        asm volatile("mma.sync.aligned.m16n8k16.row.col.f32.f16.f16.f32 "
                     "{%0,%1,%2,%3}, {%4,%5,%6,%7}, {%8,%9}, {%0,%1,%2,%3};\n"
                     : "+f"(acc[1][0]), "+f"(acc[1][1]), "+f"(acc[1][2]), "+f"(acc[1][3])
                     : "r"(a.x), "r"(a.y), "r"(a.z), "r"(a.w), "r"(b0.z), "r"(b0.w));
        asm volatile("mma.sync.aligned.m16n8k16.row.col.f32.f16.f16.f32 "
                     "{%0,%1,%2,%3}, {%4,%5,%6,%7}, {%8,%9}, {%0,%1,%2,%3};\n"
                     : "+f"(acc[2][0]), "+f"(acc[2][1]), "+f"(acc[2][2]), "+f"(acc[2][3])
                     : "r"(a.x), "r"(a.y), "r"(a.z), "r"(a.w), "r"(b1v.x), "r"(b1v.y));
        asm volatile("mma.sync.aligned.m16n8k16.row.col.f32.f16.f16.f32 "
                     "{%0,%1,%2,%3}, {%4,%5,%6,%7}, {%8,%9}, {%0,%1,%2,%3};\n"
                     : "+f"(acc[3][0]), "+f"(acc[3][1]), "+f"(acc[3][2]), "+f"(acc[3][3])
                     : "r"(a.x), "r"(a.y), "r"(a.z), "r"(a.w), "r"(b1v.z), "r"(b1v.w));
    }

    // h1 -> smem with bias+clip
    #pragma unroll
    for (int nb = 0; nb < 4; ++nb) {
        const int col = nb * 8 + 2 * t4;
        const int r0 = wid * 16 + g, r1 = r0 + 8;
        sh1[r0 * 33 + col]     = __saturatef(acc[nb][0] + sb1[col]);
        sh1[r0 * 33 + col + 1] = __saturatef(acc[nb][1] + sb1[col + 1]);
        sh1[r1 * 33 + col]     = __saturatef(acc[nb][2] + sb1[col]);
        sh1[r1 * 33 + col + 1] = __saturatef(acc[nb][3] + sb1[col + 1]);
    }
    __syncthreads();

    if (tid < 128) {
        const int r = sperm[tid];
        if (r >= 0) {
            const float* hr = &sh1[tid * 33];
            float o = 0.f;
            #pragma unroll 4
            for (int ii = 0; ii < 32; ++ii) {
                float s = sb2[ii];
                const float* wr = &sW2[ii * 32];
                #pragma unroll
                for (int jj = 0; jj < 32; ++jj) s += wr[jj] * hr[jj];
                s = __saturatef(s);
                o += sW3[ii] * s;
            }
            o += sb3v + 0.5f * (g_psqt_s[r] - g_psqt_n[r]);
            out[r] = o;
        }
    }
}

// ---------------- launch ----------------
extern "C" void kernel_launch(void* const* d_in, const int* in_sizes, int n_in,
                              void* d_out, int out_size) {
    const float* stm  = (const float*)d_in[0];
    const float* nstm = (const float*)d_in[1];
    const float* Wacc = (const float*)d_in[2];
    const float* bacc = (const float*)d_in[3];
    const float* W1   = (const float*)d_in[4];
    const float* b1   = (const float*)d_in[5];
    const float* W2   = (const float*)d_in[6];
    const float* b2   = (const float*)d_in[7];
    const float* W3   = (const float*)d_in[8];
    const float* b3   = (const float*)d_in[9];
    float* out = (float*)d_out;

    static bool attr_set = false;
    if (!attr_set) {
        cudaFuncSetAttribute(gemm1_kernel, cudaFuncAttributeMaxDynamicSharedMemorySize, G1_SMEM);
        attr_set = true;
    }

    prep_kernel<<<FEAT_BASE + BATCH / 8, 256>>>(stm, nstm, Wacc, W1);
    snap_kernel<<<1, 32>>>();

    dim3 g1(18, ACCN / 128);
    gemm1_kernel<<<g1, 512, G1_SMEM>>>(bacc);

    gemm2_kernel<<<MAXT2, 256>>>(b1, W2, b2, W3, b3, out);
}